// round 6
// baseline (speedup 1.0000x reference)
#include <cuda_runtime.h>
#include <cstdint>
#include <math.h>

#define LC   2048
#define CINV 0.35355339059327373f   // 1/(2*sqrt(2))

typedef unsigned long long u64;

// Scratch: transposed weights [which][k][i*64+o], corrections [k][which][b][o]
__device__ float g_wt[2][(size_t)LC * 4096];
__device__ float g_ad[(size_t)LC * 4096];

// packed f32x2 FMA: acc(2 lanes) += a(2 lanes) * b(2 lanes)
__device__ __forceinline__ void fma2(u64& acc, u64 a, u64 b) {
    asm("fma.rn.f32x2 %0, %1, %2, %0;" : "+l"(acc) : "l"(a), "l"(b));
}
__device__ __forceinline__ float lo32(u64 v) { return __uint_as_float((unsigned)v); }
__device__ __forceinline__ float hi32(u64 v) { return __uint_as_float((unsigned)(v >> 32)); }

__device__ __forceinline__ float gelu_tanh(float v) {
    float z = 0.7978845608028654f * (v + 0.044715f * v * v * v);
    float t;
    asm("tanh.approx.f32 %0, %1;" : "=f"(t) : "f"(z));
    return 0.5f * v * (1.0f + t);
}

// ---------------------------------------------------------------------------
// Kernel 1: transpose w_approx / w_detail from (i,o,l) -> (l, i*64+o)
// ---------------------------------------------------------------------------
__global__ void transpose_w_kernel(const float* __restrict__ wA,
                                   const float* __restrict__ wD) {
    __shared__ float tile[32][33];
    const float* src = (blockIdx.z == 0) ? wA : wD;
    float* dst = g_wt[blockIdx.z];
    int lbase  = blockIdx.x * 32;
    int iobase = blockIdx.y * 32;
    int tx = threadIdx.x, ty = threadIdx.y;   // block (32, 8)
#pragma unroll
    for (int r = 0; r < 32; r += 8)
        tile[ty + r][tx] = src[(size_t)(iobase + ty + r) * LC + (lbase + tx)];
    __syncthreads();
#pragma unroll
    for (int r = 0; r < 32; r += 8)
        dst[(size_t)(lbase + ty + r) * 4096 + (iobase + tx)] = tile[tx][ty + r];
}

// ---------------------------------------------------------------------------
// Kernel 2: fused u/v + corrections (UNCHANGED from R5 — proven).
// ---------------------------------------------------------------------------
__global__ __launch_bounds__(256, 4) void stagea_kernel(const float* __restrict__ x) {
    extern __shared__ float sm[];
    float* wsm = sm;           // [2][4096]
    float* us  = sm + 8192;    // [2][i*33+b]

    const int k = blockIdx.x, tid = threadIdx.x;

    for (int i = tid; i < 4096; i += 256) {
        wsm[i]        = g_wt[0][(size_t)k * 4096 + i];
        wsm[4096 + i] = g_wt[1][(size_t)k * 4096 + i];
    }
    for (int p = tid; p < 2048; p += 256) {
        int i = p & 63, b = p >> 6;
        const float* xp = x + ((size_t)b * 16384 + (size_t)k * 8) * 64 + i;
        float e = 0.f, d = 0.f;
#pragma unroll
        for (int j = 0; j < 4; j++) { e += xp[j * 64]; d += xp[(j + 4) * 64]; }
        us[i * 33 + b]        = CINV * (e + d);
        us[2112 + i * 33 + b] = CINV * (e - d);
    }
    __syncthreads();

    const int which = tid >> 7;
    const int r  = tid & 127;
    const int b0 = (r >> 4) * 4;
    const int og = (r & 15) * 4;
    const float* W = wsm + which * 4096;
    const float* U = us + which * 2112;

    float acc[4][4] = {};
#pragma unroll 8
    for (int i = 0; i < 64; i++) {
        float4 w4 = *(const float4*)(W + i * 64 + og);
#pragma unroll
        for (int bb = 0; bb < 4; bb++) {
            float uu = U[i * 33 + b0 + bb];
            acc[bb][0] = fmaf(uu, w4.x, acc[bb][0]);
            acc[bb][1] = fmaf(uu, w4.y, acc[bb][1]);
            acc[bb][2] = fmaf(uu, w4.z, acc[bb][2]);
            acc[bb][3] = fmaf(uu, w4.w, acc[bb][3]);
        }
    }
    float* adg = g_ad + (size_t)k * 4096 + which * 2048;
#pragma unroll
    for (int bb = 0; bb < 4; bb++)
#pragma unroll
        for (int c = 0; c < 4; c++)
            adg[(b0 + bb) * 64 + og + c] =
                CINV * (acc[bb][c] - U[(og + c) * 33 + b0 + bb]);
}

// ---------------------------------------------------------------------------
// Kernel 3: main GEMM + epilogue, f32x2-packed (K paired into the two lanes).
// Same block structure as R5: grid 4096 = (k, half), 256 threads, 128 rows,
// 8x4 output tile per thread, occupancy 3.
// Weights K-paired in smem: w2f[kk2][c][2] = {W'[2kk2][c], W'[2kk2+1][c]}
// so a thread's 4 columns are 4 contiguous u64 -> two LDS.128, zero packing.
// ---------------------------------------------------------------------------
__global__ __launch_bounds__(256, 3) void main_kernel(
    const float* __restrict__ x, const float* __restrict__ Ws,
    const float* __restrict__ bsk, float* __restrict__ out)
{
    extern __shared__ float sm[];
    float* xs   = sm;            // 16 b * 520 = 8320
    float* w2f  = sm + 8320;     // 4096  K-paired (W_skip + I)
    float* ads  = sm + 12416;    // 2048  [which][16 b][64 o]
    float* bias = sm + 14464;    // 64    (total 14528 floats = 58112 B)

    const int k    = blockIdx.x >> 1;
    const int half = blockIdx.x & 1;
    const int tid  = threadIdx.x;

    for (int i = tid; i < 4096; i += 256) {
        int kk = i >> 6, c = i & 63;
        float v = Ws[i] + ((kk == c) ? 1.f : 0.f);
        w2f[(kk >> 1) * 128 + c * 2 + (kk & 1)] = v;
    }
    for (int i = tid; i < 2048; i += 256) {
        int which = i >> 10, bl = (i >> 6) & 15, o = i & 63;
        ads[i] = g_ad[(size_t)k * 4096 + which * 2048 + (half * 16 + bl) * 64 + o];
    }
    if (tid < 64) bias[tid] = bsk[tid];

    const float4* x4  = (const float4*)x;
    float4*       xs4 = (float4*)xs;
#pragma unroll
    for (int it = 0; it < 8; it++) {
        int idx = tid + it * 256;           // 0..2047 float4s
        int bl = idx >> 7, r = idx & 127;
        int b  = half * 16 + bl;
        xs4[bl * 130 + r] = x4[(size_t)b * 262144 + (size_t)k * 128 + r];
    }
    __syncthreads();

    const int bl = tid >> 4;
    const int cg = (tid & 15) << 2;
    const float* xb = xs + bl * 520;
    const u64*   W2 = (const u64*)w2f;      // [kk2*64 + c]

    u64 acc[8][4] = {};
#pragma unroll 8
    for (int kk2 = 0; kk2 < 32; kk2++) {
        ulonglong2 wA = *(const ulonglong2*)(W2 + kk2 * 64 + cg);      // cols cg, cg+1
        ulonglong2 wB = *(const ulonglong2*)(W2 + kk2 * 64 + cg + 2);  // cols cg+2, cg+3
#pragma unroll
        for (int j = 0; j < 8; j++) {
            u64 xj = *(const u64*)(xb + j * 64 + kk2 * 2);
            fma2(acc[j][0], xj, wA.x);
            fma2(acc[j][1], xj, wA.y);
            fma2(acc[j][2], xj, wB.x);
            fma2(acc[j][3], xj, wB.y);
        }
    }

    float4 A  = *(const float4*)(ads + bl * 64 + cg);
    float4 Dv = *(const float4*)(ads + 1024 + bl * 64 + cg);
    float4 Bb = *(const float4*)(bias + cg);
    const int b = half * 16 + bl;
    float* op = out + ((size_t)b * 16384 + (size_t)k * 8) * 64 + cg;
#pragma unroll
    for (int j = 0; j < 8; j++) {
        float sgn = (j < 4) ? 1.f : -1.f;
        float4 rv;
        rv.x = gelu_tanh(lo32(acc[j][0]) + hi32(acc[j][0]) + A.x + sgn * Dv.x + Bb.x);
        rv.y = gelu_tanh(lo32(acc[j][1]) + hi32(acc[j][1]) + A.y + sgn * Dv.y + Bb.y);
        rv.z = gelu_tanh(lo32(acc[j][2]) + hi32(acc[j][2]) + A.z + sgn * Dv.z + Bb.z);
        rv.w = gelu_tanh(lo32(acc[j][3]) + hi32(acc[j][3]) + A.w + sgn * Dv.w + Bb.w);
        *(float4*)(op + j * 64) = rv;
    }
}

extern "C" void kernel_launch(void* const* d_in, const int* in_sizes, int n_in,
                              void* d_out, int out_size) {
    const float* x  = (const float*)d_in[0];   // (32, 16384, 64)
    const float* wA = (const float*)d_in[1];   // (64, 64, 2048)
    const float* wD = (const float*)d_in[2];   // (64, 64, 2048)
    const float* Ws = (const float*)d_in[3];   // (64, 64)
    const float* bs = (const float*)d_in[4];   // (64,)
    float* out = (float*)d_out;

    cudaFuncSetAttribute(stagea_kernel,
        cudaFuncAttributeMaxDynamicSharedMemorySize, 49664);
    cudaFuncSetAttribute(main_kernel,
        cudaFuncAttributeMaxDynamicSharedMemorySize, 58112);

    dim3 tb(32, 8), tg(LC / 32, 4096 / 32, 2);
    transpose_w_kernel<<<tg, tb>>>(wA, wD);

    stagea_kernel<<<LC, 256, 49664>>>(x);

    main_kernel<<<2 * LC, 256, 58112>>>(x, Ws, bs, out);
}

// round 7
// speedup vs baseline: 1.8072x; 1.8072x over previous
#include <cuda_runtime.h>
#include <cstdint>
#include <math.h>

#define LC   2048
#define CINV 0.35355339059327373f   // 1/(2*sqrt(2))

// Scratch: transposed weights [which][k][i*64+o]
__device__ float g_wt[2][(size_t)LC * 4096];

__device__ __forceinline__ float gelu_tanh(float v) {
    float z = 0.7978845608028654f * (v + 0.044715f * v * v * v);
    float t;
    asm("tanh.approx.f32 %0, %1;" : "=f"(t) : "f"(z));
    return 0.5f * v * (1.0f + t);
}

// ---------------------------------------------------------------------------
// Kernel 1: transpose w_approx / w_detail from (i,o,l) -> (l, i*64+o)
// ---------------------------------------------------------------------------
__global__ void transpose_w_kernel(const float* __restrict__ wA,
                                   const float* __restrict__ wD) {
    __shared__ float tile[32][33];
    const float* src = (blockIdx.z == 0) ? wA : wD;
    float* dst = g_wt[blockIdx.z];
    int lbase  = blockIdx.x * 32;
    int iobase = blockIdx.y * 32;
    int tx = threadIdx.x, ty = threadIdx.y;   // block (32, 8)
#pragma unroll
    for (int r = 0; r < 32; r += 8)
        tile[ty + r][tx] = src[(size_t)(iobase + ty + r) * LC + (lbase + tx)];
    __syncthreads();
#pragma unroll
    for (int r = 0; r < 32; r += 8)
        dst[(size_t)(lbase + ty + r) * 4096 + (iobase + tx)] = tile[tx][ty + r];
}

// ---------------------------------------------------------------------------
// Kernel 2: fully fused — u/v, corrections, GEMM, epilogue in one kernel.
// Grid 4096 = (k, half). Block: 256 threads, 16 batches x 8 rows x 64 ch.
//
// Phase 0: xs <- x tile; shr <- W_t[k] (both which); bias.
// Phase 1: uv[which][i][b]  (from xs)
// Phase 2: corr[which][b][o] = CINV*(sum_i uv[i][b]*W[i][o] - uv[o][b])
// Phase 3: shr[0:4096) <- (W_skip + I)   (overwrites W_t region)
// Phase 4: GEMM C = X.(W_skip+I) (proven R5 8x4 scalar tile) + epilogue.
// ---------------------------------------------------------------------------
__global__ __launch_bounds__(256, 2) void fused_kernel(
    const float* __restrict__ x, const float* __restrict__ Ws,
    const float* __restrict__ bsk, float* __restrict__ out)
{
    extern __shared__ float sm[];
    float* xs   = sm;            // 16 b * 520 (8x64 + pad 8)      = 8320
    float* shr  = sm + 8320;     // phase1: W_t [2][4096]; phase3: wsk [4096]
    float* uv   = sm + 16512;    // [2][64 i][20 pad]              = 2560
    float* corr = sm + 19072;    // [2][16 b][64 o]                = 2048
    float* bias = sm + 21120;    // 64    (total 21184 fl = 84736 B)

    const int k    = blockIdx.x >> 1;
    const int half = blockIdx.x & 1;
    const int tid  = threadIdx.x;

    // ---- Phase 0: loads ----
    const float4* x4  = (const float4*)x;
    float4*       xs4 = (float4*)xs;
#pragma unroll
    for (int it = 0; it < 8; it++) {
        int idx = tid + it * 256;           // 0..2047 float4s
        int bl = idx >> 7, r = idx & 127;
        int b  = half * 16 + bl;
        xs4[bl * 130 + r] = x4[(size_t)b * 262144 + (size_t)k * 128 + r];
    }
    {
        const float4* wt0 = (const float4*)(g_wt[0] + (size_t)k * 4096);
        const float4* wt1 = (const float4*)(g_wt[1] + (size_t)k * 4096);
        float4* shr4 = (float4*)shr;
#pragma unroll
        for (int it = 0; it < 4; it++) {
            int i = tid + it * 256;         // 0..1023 float4s
            shr4[i]        = wt0[i];
            shr4[1024 + i] = wt1[i];
        }
    }
    if (tid < 64) bias[tid] = bsk[tid];
    __syncthreads();

    // ---- Phase 1: u/v.  p -> (which, b, i); consecutive tid = consecutive i.
    for (int p = tid; p < 2048; p += 256) {
        int i = p & 63, bl = (p >> 6) & 15, which = p >> 10;
        const float* xb = xs + bl * 520 + i;
        float e = 0.f, d = 0.f;
#pragma unroll
        for (int j = 0; j < 4; j++) { e += xb[j * 64]; d += xb[(j + 4) * 64]; }
        uv[which * 1280 + i * 20 + bl] = (which == 0) ? CINV * (e + d)
                                                      : CINV * (e - d);
    }
    __syncthreads();

    // ---- Phase 2: corrections. thread -> (which, b, 8 outputs og..og+7)
    {
        const int which = tid >> 7;
        const int r  = tid & 127;
        const int bl = r >> 3;
        const int og = (r & 7) * 8;
        const float* W = shr + which * 4096;
        const float* U = uv + which * 1280;

        float acc[8] = {};
#pragma unroll 8
        for (int i = 0; i < 64; i++) {
            float u = U[i * 20 + bl];
            float4 w0 = *(const float4*)(W + i * 64 + og);
            float4 w1 = *(const float4*)(W + i * 64 + og + 4);
            acc[0] = fmaf(u, w0.x, acc[0]);
            acc[1] = fmaf(u, w0.y, acc[1]);
            acc[2] = fmaf(u, w0.z, acc[2]);
            acc[3] = fmaf(u, w0.w, acc[3]);
            acc[4] = fmaf(u, w1.x, acc[4]);
            acc[5] = fmaf(u, w1.y, acc[5]);
            acc[6] = fmaf(u, w1.z, acc[6]);
            acc[7] = fmaf(u, w1.w, acc[7]);
        }
        float* cp = corr + which * 1024 + bl * 64 + og;
#pragma unroll
        for (int e = 0; e < 8; e++)
            cp[e] = CINV * (acc[e] - U[(og + e) * 20 + bl]);
    }
    __syncthreads();

    // ---- Phase 3: overwrite shr with (W_skip + I) ----
#pragma unroll
    for (int it = 0; it < 16; it++) {
        int i = tid + it * 256;             // 0..4095
        float v = Ws[i];
        if ((i >> 6) == (i & 63)) v += 1.0f;
        shr[i] = v;
    }
    __syncthreads();

    // ---- Phase 4: GEMM + epilogue (proven R5 inner loop) ----
    const int bl = tid >> 4;
    const int cg = (tid & 15) << 2;
    const float* xb = xs + bl * 520;

    float acc[8][4] = {};
#pragma unroll 8
    for (int kk = 0; kk < 64; kk += 2) {
        float4 w0 = *(const float4*)(shr + kk * 64 + cg);
        float4 w1 = *(const float4*)(shr + (kk + 1) * 64 + cg);
        float2 xv[8];
#pragma unroll
        for (int j = 0; j < 8; j++)
            xv[j] = *(const float2*)(xb + j * 64 + kk);
#pragma unroll
        for (int j = 0; j < 8; j++) {
            acc[j][0] = fmaf(xv[j].x, w0.x, acc[j][0]);
            acc[j][0] = fmaf(xv[j].y, w1.x, acc[j][0]);
            acc[j][1] = fmaf(xv[j].x, w0.y, acc[j][1]);
            acc[j][1] = fmaf(xv[j].y, w1.y, acc[j][1]);
            acc[j][2] = fmaf(xv[j].x, w0.z, acc[j][2]);
            acc[j][2] = fmaf(xv[j].y, w1.z, acc[j][2]);
            acc[j][3] = fmaf(xv[j].x, w0.w, acc[j][3]);
            acc[j][3] = fmaf(xv[j].y, w1.w, acc[j][3]);
        }
    }

    float4 A  = *(const float4*)(corr + bl * 64 + cg);
    float4 Dv = *(const float4*)(corr + 1024 + bl * 64 + cg);
    float4 Bb = *(const float4*)(bias + cg);
    const int b = half * 16 + bl;
    float* op = out + ((size_t)b * 16384 + (size_t)k * 8) * 64 + cg;
#pragma unroll
    for (int j = 0; j < 8; j++) {
        float sgn = (j < 4) ? 1.f : -1.f;
        float4 rv;
        rv.x = gelu_tanh(acc[j][0] + A.x + sgn * Dv.x + Bb.x);
        rv.y = gelu_tanh(acc[j][1] + A.y + sgn * Dv.y + Bb.y);
        rv.z = gelu_tanh(acc[j][2] + A.z + sgn * Dv.z + Bb.z);
        rv.w = gelu_tanh(acc[j][3] + A.w + sgn * Dv.w + Bb.w);
        *(float4*)(op + j * 64) = rv;
    }
}

extern "C" void kernel_launch(void* const* d_in, const int* in_sizes, int n_in,
                              void* d_out, int out_size) {
    const float* x  = (const float*)d_in[0];   // (32, 16384, 64)
    const float* wA = (const float*)d_in[1];   // (64, 64, 2048)
    const float* wD = (const float*)d_in[2];   // (64, 64, 2048)
    const float* Ws = (const float*)d_in[3];   // (64, 64)
    const float* bs = (const float*)d_in[4];   // (64,)
    float* out = (float*)d_out;

    cudaFuncSetAttribute(fused_kernel,
        cudaFuncAttributeMaxDynamicSharedMemorySize, 84736);

    dim3 tb(32, 8), tg(LC / 32, 4096 / 32, 2);
    transpose_w_kernel<<<tg, tb>>>(wA, wD);

    fused_kernel<<<2 * LC, 256, 84736>>>(x, Ws, bs, out);
}

// round 8
// speedup vs baseline: 2.3775x; 1.3155x over previous
#include <cuda_runtime.h>
#include <cuda_bf16.h>
#include <cstdint>
#include <math.h>

#define LC   2048
#define CINV 0.35355339059327373f   // 1/(2*sqrt(2))

// Transposed wavelet weights, bf16: [which][k][i*64+o]
__device__ __nv_bfloat16 g_wt[2][(size_t)LC * 4096];

__device__ __forceinline__ float gelu_tanh(float v) {
    float z = 0.7978845608028654f * (v + 0.044715f * v * v * v);
    float t;
    asm("tanh.approx.f32 %0, %1;" : "=f"(t) : "f"(z));
    return 0.5f * v * (1.0f + t);
}

// ---------------------------------------------------------------------------
// Kernel 1: transpose w_approx / w_detail (i,o,l) -> (l, i*64+o), f32 -> bf16
// ---------------------------------------------------------------------------
__global__ void transpose_w_kernel(const float* __restrict__ wA,
                                   const float* __restrict__ wD) {
    __shared__ float tile[32][33];
    const float* src = (blockIdx.z == 0) ? wA : wD;
    __nv_bfloat16* dst = g_wt[blockIdx.z];
    int lbase  = blockIdx.x * 32;
    int iobase = blockIdx.y * 32;
    int tx = threadIdx.x, ty = threadIdx.y;   // block (32, 8)
#pragma unroll
    for (int r = 0; r < 32; r += 8)
        tile[ty + r][tx] = src[(size_t)(iobase + ty + r) * LC + (lbase + tx)];
    __syncthreads();
#pragma unroll
    for (int r = 0; r < 32; r += 8)
        dst[(size_t)(lbase + ty + r) * 4096 + (iobase + tx)] =
            __float2bfloat16(tile[tx][ty + r]);
}

// ---------------------------------------------------------------------------
// Kernel 2: fully fused — u/v, corrections (bf16 weights), GEMM, epilogue.
// Grid 4096 = (k, half). 256 threads, 16 batches x 8 rows x 64 ch. 3 CTAs/SM.
// shrW region dual-use: phase<=2 holds W_t bf16 (16 KB); phase>=3 wsk f32.
// ---------------------------------------------------------------------------
__global__ __launch_bounds__(256, 3) void fused_kernel(
    const float* __restrict__ x, const float* __restrict__ Ws,
    const float* __restrict__ bsk, float* __restrict__ out)
{
    extern __shared__ float sm[];
    float* xs   = sm;            // 16 b * 520 (8x64 + pad 8)   = 8320 fl
    float* shrW = sm + 8320;     // 4096 fl: bf16 W_t [2][4096] then f32 wsk
    float* uv   = sm + 12416;    // [2][64 i][21]               = 2688 fl
    float* corr = sm + 15104;    // [2][16 b][64 o]             = 2048 fl
    float* bias = sm + 17152;    // 64 fl   (total 17216 fl = 68864 B)

    const int k    = blockIdx.x >> 1;
    const int half = blockIdx.x & 1;
    const int tid  = threadIdx.x;

    // ---- Phase 0: loads ----
    const float4* x4  = (const float4*)x;
    float4*       xs4 = (float4*)xs;
#pragma unroll
    for (int it = 0; it < 8; it++) {
        int idx = tid + it * 256;           // 0..2047 float4s
        int bl = idx >> 7, r = idx & 127;
        int b  = half * 16 + bl;
        xs4[bl * 130 + r] = x4[(size_t)b * 262144 + (size_t)k * 128 + r];
    }
    {
        // W_t bf16: 2 x 4096 bf16 = 16384 B = 1024 uint4
        const uint4* wt0 = (const uint4*)(g_wt[0] + (size_t)k * 4096);
        const uint4* wt1 = (const uint4*)(g_wt[1] + (size_t)k * 4096);
        uint4* dstw = (uint4*)shrW;
#pragma unroll
        for (int it = 0; it < 2; it++) {
            int i = tid + it * 256;         // 0..511 uint4 per which
            dstw[i]       = wt0[i];
            dstw[512 + i] = wt1[i];
        }
    }
    if (tid < 64) bias[tid] = bsk[tid];
    __syncthreads();

    // ---- Phase 1: u/v.  p -> (which, b, i); consecutive tid = consecutive i.
    for (int p = tid; p < 2048; p += 256) {
        int i = p & 63, bl = (p >> 6) & 15, which = p >> 10;
        const float* xb = xs + bl * 520 + i;
        float e = 0.f, d = 0.f;
#pragma unroll
        for (int j = 0; j < 4; j++) { e += xb[j * 64]; d += xb[(j + 4) * 64]; }
        uv[which * 1344 + i * 21 + bl] = (which == 0) ? CINV * (e + d)
                                                      : CINV * (e - d);
    }
    __syncthreads();

    // ---- Phase 2: corrections. thread -> (which, b, 8 outputs og..og+7)
    {
        const int which = tid >> 7;
        const int r  = tid & 127;
        const int bl = r >> 3;
        const int og = (r & 7) * 8;
        const __nv_bfloat16* W = (const __nv_bfloat16*)shrW + which * 4096;
        const float* U = uv + which * 1344;

        float acc[8] = {};
#pragma unroll 8
        for (int i = 0; i < 64; i++) {
            float u = U[i * 21 + bl];
            // 8 bf16 weights = 16 B
            uint4 wv = *(const uint4*)(W + i * 64 + og);
            float2 w0 = __bfloat1622float2(*(const __nv_bfloat162*)&wv.x);
            float2 w1 = __bfloat1622float2(*(const __nv_bfloat162*)&wv.y);
            float2 w2 = __bfloat1622float2(*(const __nv_bfloat162*)&wv.z);
            float2 w3 = __bfloat1622float2(*(const __nv_bfloat162*)&wv.w);
            acc[0] = fmaf(u, w0.x, acc[0]);
            acc[1] = fmaf(u, w0.y, acc[1]);
            acc[2] = fmaf(u, w1.x, acc[2]);
            acc[3] = fmaf(u, w1.y, acc[3]);
            acc[4] = fmaf(u, w2.x, acc[4]);
            acc[5] = fmaf(u, w2.y, acc[5]);
            acc[6] = fmaf(u, w3.x, acc[6]);
            acc[7] = fmaf(u, w3.y, acc[7]);
        }
        float* cp = corr + which * 1024 + bl * 64 + og;
#pragma unroll
        for (int e = 0; e < 8; e++)
            cp[e] = CINV * (acc[e] - U[(og + e) * 21 + bl]);
    }
    __syncthreads();

    // ---- Phase 3: overwrite shrW with (W_skip + I) as f32 ----
#pragma unroll
    for (int it = 0; it < 16; it++) {
        int i = tid + it * 256;             // 0..4095
        float v = Ws[i];
        if ((i >> 6) == (i & 63)) v += 1.0f;
        shrW[i] = v;
    }
    __syncthreads();

    // ---- Phase 4: GEMM + epilogue (proven inner loop) ----
    const int bl = tid >> 4;
    const int cg = (tid & 15) << 2;
    const float* xb = xs + bl * 520;

    float acc[8][4] = {};
#pragma unroll 8
    for (int kk = 0; kk < 64; kk += 2) {
        float4 w0 = *(const float4*)(shrW + kk * 64 + cg);
        float4 w1 = *(const float4*)(shrW + (kk + 1) * 64 + cg);
        float2 xv[8];
#pragma unroll
        for (int j = 0; j < 8; j++)
            xv[j] = *(const float2*)(xb + j * 64 + kk);
#pragma unroll
        for (int j = 0; j < 8; j++) {
            acc[j][0] = fmaf(xv[j].x, w0.x, acc[j][0]);
            acc[j][0] = fmaf(xv[j].y, w1.x, acc[j][0]);
            acc[j][1] = fmaf(xv[j].x, w0.y, acc[j][1]);
            acc[j][1] = fmaf(xv[j].y, w1.y, acc[j][1]);
            acc[j][2] = fmaf(xv[j].x, w0.z, acc[j][2]);
            acc[j][2] = fmaf(xv[j].y, w1.z, acc[j][2]);
            acc[j][3] = fmaf(xv[j].x, w0.w, acc[j][3]);
            acc[j][3] = fmaf(xv[j].y, w1.w, acc[j][3]);
        }
    }

    float4 A  = *(const float4*)(corr + bl * 64 + cg);
    float4 Dv = *(const float4*)(corr + 1024 + bl * 64 + cg);
    float4 Bb = *(const float4*)(bias + cg);
    const int b = half * 16 + bl;
    float* op = out + ((size_t)b * 16384 + (size_t)k * 8) * 64 + cg;
#pragma unroll
    for (int j = 0; j < 8; j++) {
        float sgn = (j < 4) ? 1.f : -1.f;
        float4 rv;
        rv.x = gelu_tanh(acc[j][0] + A.x + sgn * Dv.x + Bb.x);
        rv.y = gelu_tanh(acc[j][1] + A.y + sgn * Dv.y + Bb.y);
        rv.z = gelu_tanh(acc[j][2] + A.z + sgn * Dv.z + Bb.z);
        rv.w = gelu_tanh(acc[j][3] + A.w + sgn * Dv.w + Bb.w);
        *(float4*)(op + j * 64) = rv;
    }
}

extern "C" void kernel_launch(void* const* d_in, const int* in_sizes, int n_in,
                              void* d_out, int out_size) {
    const float* x  = (const float*)d_in[0];   // (32, 16384, 64)
    const float* wA = (const float*)d_in[1];   // (64, 64, 2048)
    const float* wD = (const float*)d_in[2];   // (64, 64, 2048)
    const float* Ws = (const float*)d_in[3];   // (64, 64)
    const float* bs = (const float*)d_in[4];   // (64,)
    float* out = (float*)d_out;

    cudaFuncSetAttribute(fused_kernel,
        cudaFuncAttributeMaxDynamicSharedMemorySize, 68864);

    dim3 tb(32, 8), tg(LC / 32, 4096 / 32, 2);
    transpose_w_kernel<<<tg, tb>>>(wA, wD);

    fused_kernel<<<2 * LC, 256, 68864>>>(x, Ws, bs, out);
}